// round 17
// baseline (speedup 1.0000x reference)
#include <cuda_runtime.h>
#include <cuda_bf16.h>
#include <math_constants.h>
#include <cstdint>

#define L     8192
#define D     64
#define BM    128            // query rows per CTA
#define NCH   16
#define CHUNK 512            // L / NCH
#define BN1   64             // pass1 key-tile width
#define T1    8              // CHUNK / BN1
#define BN2   64             // pass2 key-tile width
#define T2    8              // CHUNK / BN2
#define NT    256
#define NRB   (L / BM)       // 64 row blocks
#define PGX   (L * D / (2 * 256))   // 1024 prep CTAs per plane

// ---------------- scratch (__device__ globals; no allocation allowed) -------
__device__ float g_l[L];     // row sums of exp(s), atomically accumulated
__device__ int   g_cnt[NRB]; // per-rowblock pass1 completion counters
__device__ int   g_prep[4];  // per-plane prep completion counters (Q,K,V,zero)
__device__ int   g_done;     // pass2 completion counter (for reset)
// 2-limb bf16 versions of Q, K, V (prep kernel fills once)
__device__ __nv_bfloat16 gQh[L * D], gQl[L * D];
__device__ __nv_bfloat16 gKh[L * D], gKl[L * D];
__device__ __nv_bfloat16 gVh[L * D], gVl[L * D];

// ---------------- helpers ---------------------------------------------------
__device__ __forceinline__ uint32_t smem_to_u32(const void* p) {
    uint32_t a;
    asm("{ .reg .u64 t; cvta.to.shared.u64 t, %1; cvt.u32.u64 %0, t; }"
        : "=r"(a) : "l"(p));
    return a;
}
#define CP_ASYNC16(dst, src) \
    asm volatile("cp.async.cg.shared.global [%0], [%1], 16;" \
                 :: "r"(dst), "l"(src) : "memory")
#define CP_COMMIT() asm volatile("cp.async.commit_group;" ::: "memory")
#define CP_WAIT(n)  asm volatile("cp.async.wait_group %0;" :: "n"(n) : "memory")

__device__ __forceinline__ int ld_acq(const int* p) {
    int v;
    asm volatile("ld.acquire.gpu.global.s32 %0, [%1];"
                 : "=r"(v) : "l"(p) : "memory");
    return v;
}
__device__ __forceinline__ void ldsm_x4(uint32_t* r, uint32_t a) {
    asm volatile("ldmatrix.sync.aligned.m8n8.x4.shared.b16 {%0,%1,%2,%3}, [%4];"
                 : "=r"(r[0]), "=r"(r[1]), "=r"(r[2]), "=r"(r[3]) : "r"(a));
}
__device__ __forceinline__ void ldsm_x4_t(uint32_t* r, uint32_t a) {
    asm volatile("ldmatrix.sync.aligned.m8n8.x4.trans.shared.b16 {%0,%1,%2,%3}, [%4];"
                 : "=r"(r[0]), "=r"(r[1]), "=r"(r[2]), "=r"(r[3]) : "r"(a));
}
__device__ __forceinline__ void mma_bf16(float* c, const uint32_t* a,
                                         uint32_t b0, uint32_t b1) {
    asm volatile("mma.sync.aligned.m16n8k16.row.col.f32.bf16.bf16.f32 "
                 "{%0,%1,%2,%3}, {%4,%5,%6,%7}, {%8,%9}, {%0,%1,%2,%3};"
                 : "+f"(c[0]), "+f"(c[1]), "+f"(c[2]), "+f"(c[3])
                 : "r"(a[0]), "r"(a[1]), "r"(a[2]), "r"(a[3]), "r"(b0), "r"(b1));
}
__device__ __forceinline__ void split2(float x, float y,
                                       __nv_bfloat162& h2, __nv_bfloat162& l2) {
    __nv_bfloat16 hx = __float2bfloat16(x);
    __nv_bfloat16 hy = __float2bfloat16(y);
    h2.x = hx; h2.y = hy;
    l2.x = __float2bfloat16(x - __bfloat162float(hx));
    l2.y = __float2bfloat16(y - __bfloat162float(hy));
}
// SW128 swizzle: 128B rows, 16B chunks; chunk c of row r lives at c^(r&7)
__device__ __forceinline__ uint32_t swo(int r, int c16) {
    return (uint32_t)(r * 128 + ((c16 ^ (r & 7)) << 4));
}

// pass1 smem byte offsets (swizzled 128B rows)
#define SQH 0
#define SQL 16384
#define SK0 32768              // buf b at SK0 + b*16384 (hi +0, lo +8192)
#define P1_SMEM  65536
// pass2 smem byte offsets
#define SPH 0
#define SPL 16384
#define SV0 32768              // buf b at SV0 + b*16384 (hi +0, lo +8192)
#define P2_STATS 65536
#define P2_SMEM  (65536 + 512)

// ---------------------------------------------------------------------------
// Prep: split Q, K, V into bf16 hi/lo limb arrays; y==3 zeroes O, g_l, g_cnt.
// Signals per-plane completion (g_prep) so pass1/pass2 can launch under PDL.
// ---------------------------------------------------------------------------
__global__ void prep_kernel(const float* __restrict__ Q,
                            const float* __restrict__ Km,
                            const float* __restrict__ V,
                            float* __restrict__ O) {
    asm volatile("griddepcontrol.launch_dependents;");
    const int idx = blockIdx.x * 256 + threadIdx.x;    // float2 index
    if (blockIdx.y == 3) {
        if (idx < L * D / 4)
            *(float4*)&O[idx * 4] = make_float4(0.f, 0.f, 0.f, 0.f);
        if (idx < L / 4)
            *(float4*)&g_l[idx * 4] = make_float4(0.f, 0.f, 0.f, 0.f);
        if (idx < NRB) g_cnt[idx] = 0;
    } else {
        const float* src; __nv_bfloat16 *dh, *dl;
        if (blockIdx.y == 0)      { src = Q;  dh = gQh; dl = gQl; }
        else if (blockIdx.y == 1) { src = Km; dh = gKh; dl = gKl; }
        else                      { src = V;  dh = gVh; dl = gVl; }
        const float2 v = *(const float2*)&src[idx * 2];
        __nv_bfloat162 h2, l2; split2(v.x, v.y, h2, l2);
        *(__nv_bfloat162*)&dh[idx * 2] = h2;
        *(__nv_bfloat162*)&dl[idx * 2] = l2;
    }
    __threadfence();
    __syncthreads();
    if (threadIdx.x == 0) atomicAdd(&g_prep[blockIdx.y], 1);
}

// ---------------------------------------------------------------------------
// Pass 1: S = exp(Q K^T) + row sums; gated on prep Q/K planes; signals
// per-rowblock completion flags for pass2.
// ---------------------------------------------------------------------------
__global__ __launch_bounds__(NT, 3) void pass1_kernel(float* __restrict__ S) {
    asm volatile("griddepcontrol.launch_dependents;");

    extern __shared__ char smem[];
    const uint32_t sb = smem_to_u32(smem);
    const int tid  = threadIdx.x;
    const int lane = tid & 31;
    const int w    = tid >> 5;
    const int wr   = (w & 3) * 32;
    const int wc   = (w >> 2) * 32;
    const int rowblk  = blockIdx.y * BM;
    const int colbase = blockIdx.x * CHUNK;

    // gate: Q and K limb planes (and zero plane, which resets g_cnt) ready
    if (tid == 0) {
        while (ld_acq(&g_prep[0]) < PGX || ld_acq(&g_prep[1]) < PGX ||
               ld_acq(&g_prep[3]) < PGX)
            __nanosleep(64);
    }
    __syncthreads();

#pragma unroll
    for (int i = 0; i < 8; i++) {
        const int idx = tid + i * NT;                // 2048 chunks
        const int limb = idx >> 10, rem = idx & 1023;
        const int r = rem >> 3, c = rem & 7;
        const __nv_bfloat16* src =
            (limb ? gQl : gQh) + (size_t)(rowblk + r) * D + c * 8;
        CP_ASYNC16(sb + (limb ? SQL : SQH) + swo(r, c), src);
    }
#pragma unroll
    for (int i = 0; i < 4; i++) {
        const int idx = tid + i * NT;                // 1024 chunks
        const int limb = idx >> 9, rem = idx & 511;
        const int r = rem >> 3, c = rem & 7;
        const __nv_bfloat16* src =
            (limb ? gKl : gKh) + (size_t)(colbase + r) * D + c * 8;
        CP_ASYNC16(sb + SK0 + limb * 8192 + swo(r, c), src);
    }
    CP_COMMIT();

    const int a_row = (lane & 7) + (lane & 8);
    const int a_c   = (lane >> 4) & 1;
    const int b_n   = (lane & 7) + ((lane >> 4) & 1) * 8;
    const int b_c   = (lane >> 3) & 1;
    const int g = lane >> 2, tq = lane & 3;

    float rsum[2][2] = {{0.f, 0.f}, {0.f, 0.f}};

    for (int t = 0; t < T1; t++) {
        CP_WAIT(0);
        __syncthreads();

        if (t + 1 < T1) {
            const int kb1 = colbase + (t + 1) * BN1;
            const uint32_t kd = sb + SK0 + ((t + 1) & 1) * 16384;
#pragma unroll
            for (int i = 0; i < 4; i++) {
                const int idx = tid + i * NT;
                const int limb = idx >> 9, rem = idx & 511;
                const int r = rem >> 3, c = rem & 7;
                const __nv_bfloat16* src =
                    (limb ? gKl : gKh) + (size_t)(kb1 + r) * D + c * 8;
                CP_ASYNC16(kd + limb * 8192 + swo(r, c), src);
            }
            CP_COMMIT();
        }

        const int kb = colbase + t * BN1;
        const uint32_t skh = sb + SK0 + (t & 1) * 16384;
        const uint32_t skl = skh + 8192;

        float acc[2][4][4];
#pragma unroll
        for (int i = 0; i < 2; i++)
#pragma unroll
            for (int j = 0; j < 4; j++)
#pragma unroll
                for (int e = 0; e < 4; e++) acc[i][j][e] = 0.0f;

#pragma unroll
        for (int ks = 0; ks < 4; ks++) {
            uint32_t aH[2][4], aL[2][4];
#pragma unroll
            for (int i = 0; i < 2; i++) {
                const uint32_t ao = swo(wr + 16 * i + a_row, ks * 2 + a_c);
                ldsm_x4(aH[i], sb + SQH + ao);
                ldsm_x4(aL[i], sb + SQL + ao);
            }
#pragma unroll
            for (int jj = 0; jj < 2; jj++) {
                const uint32_t bo = swo(wc + jj * 16 + b_n, ks * 2 + b_c);
                uint32_t bh[4], bl[4];
                ldsm_x4(bh, skh + bo);
                ldsm_x4(bl, skl + bo);
#pragma unroll
                for (int i = 0; i < 2; i++)
#pragma unroll
                    for (int p = 0; p < 2; p++) {
                        float* c = acc[i][2 * jj + p];
                        mma_bf16(c, aH[i], bh[2 * p], bh[2 * p + 1]);
                        mma_bf16(c, aH[i], bl[2 * p], bl[2 * p + 1]);
                        mma_bf16(c, aL[i], bh[2 * p], bh[2 * p + 1]);
                    }
            }
        }

#pragma unroll
        for (int i = 0; i < 2; i++) {
            const int ra = rowblk + wr + 16 * i + g;
            const int cb = kb + wc + 2 * tq;
#pragma unroll
            for (int j = 0; j < 4; j++) {
                const float e0 = __expf(acc[i][j][0]);
                const float e1 = __expf(acc[i][j][1]);
                const float e2 = __expf(acc[i][j][2]);
                const float e3 = __expf(acc[i][j][3]);
                *(float2*)&S[(size_t)ra * L + cb + 8 * j] = make_float2(e0, e1);
                *(float2*)&S[(size_t)(ra + 8) * L + cb + 8 * j] = make_float2(e2, e3);
                rsum[i][0] += e0 + e1;
                rsum[i][1] += e2 + e3;
            }
        }
    }

    // row sums -> g_l
#pragma unroll
    for (int i = 0; i < 2; i++)
#pragma unroll
        for (int h = 0; h < 2; h++) {
            float s = rsum[i][h];
            s += __shfl_xor_sync(0xffffffffu, s, 1);
            s += __shfl_xor_sync(0xffffffffu, s, 2);
            if (tq == 0)
                atomicAdd(&g_l[rowblk + wr + 16 * i + 8 * h + g], s);
        }

    // publish completion of this (chunk, rowblock)
    __threadfence();
    __syncthreads();
    if (tid == 0) atomicAdd(&g_cnt[blockIdx.y], 1);
}

// ---------------------------------------------------------------------------
// Pass 2: gated on (rowblock pass1 flags) AND (prep V plane); normalize S in
// place (streaming store) and accumulate O. Last CTA resets PDL counters.
// ---------------------------------------------------------------------------
__global__ __launch_bounds__(NT, 2) void pass2_kernel(float* __restrict__ S,
                                                      float* __restrict__ O) {
    extern __shared__ char smem[];
    const uint32_t sb = smem_to_u32(smem);
    const int tid  = threadIdx.x;
    const int lane = tid & 31;
    const int w    = tid >> 5;
    const int wr   = 16 * w;
    const int rowblk  = blockIdx.y * BM;
    const int colbase = blockIdx.x * CHUNK;

    // gate: this rowblock's pass1 chunks + V limb plane ready
    if (tid == 0) {
        while (ld_acq(&g_cnt[blockIdx.y]) < NCH || ld_acq(&g_prep[2]) < PGX)
            __nanosleep(64);
    }
    __syncthreads();

    float* li_s = (float*)(smem + P2_STATS);
    if (tid < 128) li_s[tid] = 1.0f / g_l[rowblk + tid];

    // prologue: V tile 0
#pragma unroll
    for (int i = 0; i < 4; i++) {
        const int idx = tid + i * NT;                // 1024 chunks
        const int limb = idx >> 9, rem = idx & 511;
        const int r = rem >> 3, c = rem & 7;
        const __nv_bfloat16* src =
            (limb ? gVl : gVh) + (size_t)(colbase + r) * D + c * 8;
        CP_ASYNC16(sb + SV0 + limb * 8192 + swo(r, c), src);
    }
    CP_COMMIT();

    // S tile 0 into regs (warp-local rows)
    float4 s4[8];
#pragma unroll
    for (int i = 0; i < 8; i++) {
        const int idx = i * 32 + lane;
        const int rl = idx >> 4, c4 = idx & 15;
        s4[i] = *(const float4*)&S[(size_t)(rowblk + wr + rl) * L +
                                   colbase + c4 * 4];
    }

    float acc[8][4];
#pragma unroll
    for (int j = 0; j < 8; j++)
#pragma unroll
        for (int e = 0; e < 4; e++) acc[j][e] = 0.0f;

    const int a_row = (lane & 7) + (lane & 8);
    const int a_c   = (lane >> 4) & 1;
    const int bt_k  = (lane & 7) + (lane & 8);
    const int bt_c  = (lane >> 4) & 1;

    for (int t = 0; t < T2; t++) {
        const int kb = colbase + t * BN2;

        CP_WAIT(0);
        __syncthreads();

        if (t + 1 < T2) {
            const int kb1 = colbase + (t + 1) * BN2;
            const uint32_t vd = sb + SV0 + ((t + 1) & 1) * 16384;
#pragma unroll
            for (int i = 0; i < 4; i++) {
                const int idx = tid + i * NT;
                const int limb = idx >> 9, rem = idx & 511;
                const int r = rem >> 3, c = rem & 7;
                const __nv_bfloat16* src =
                    (limb ? gVl : gVh) + (size_t)(kb1 + r) * D + c * 8;
                CP_ASYNC16(vd + limb * 8192 + swo(r, c), src);
            }
            CP_COMMIT();
        }

#pragma unroll
        for (int i = 0; i < 8; i++) {
            const int idx = i * 32 + lane;
            const int rl = idx >> 4, c4 = idx & 15;
            const int r = wr + rl;
            const float sc = li_s[r];
            float4 p4;
            p4.x = s4[i].x * sc;
            p4.y = s4[i].y * sc;
            p4.z = s4[i].z * sc;
            p4.w = s4[i].w * sc;
            if (t + 1 < T2)
                s4[i] = *(const float4*)&S[(size_t)(rowblk + r) * L +
                                           kb + BN2 + c4 * 4];
            // streaming store: normalized S is never re-read by us
            __stcs((float4*)&S[(size_t)(rowblk + r) * L + kb + c4 * 4], p4);
            const uint32_t off = swo(r, c4 >> 1) + (c4 & 1) * 8;
            __nv_bfloat162 h2a, l2a, h2b, l2b;
            split2(p4.x, p4.y, h2a, l2a);
            split2(p4.z, p4.w, h2b, l2b);
            uint2 hp, lp;
            hp.x = *(uint32_t*)&h2a; hp.y = *(uint32_t*)&h2b;
            lp.x = *(uint32_t*)&l2a; lp.y = *(uint32_t*)&l2b;
            *(uint2*)(smem + SPH + off) = hp;
            *(uint2*)(smem + SPL + off) = lp;
        }
        __syncwarp();

        const uint32_t svh = sb + SV0 + (t & 1) * 16384;
        const uint32_t svl = svh + 8192;
#pragma unroll
        for (int ks = 0; ks < 4; ks++) {
            uint32_t aH[4], aL[4];
            const uint32_t ao = swo(wr + a_row, ks * 2 + a_c);
            ldsm_x4(aH, sb + SPH + ao);
            ldsm_x4(aL, sb + SPL + ao);
#pragma unroll
            for (int jj = 0; jj < 4; jj++) {
                const uint32_t bo = swo(ks * 16 + bt_k, 2 * jj + bt_c);
                uint32_t bh[4], bl[4];
                ldsm_x4_t(bh, svh + bo);
                ldsm_x4_t(bl, svl + bo);
#pragma unroll
                for (int p = 0; p < 2; p++) {
                    float* c = acc[2 * jj + p];
                    mma_bf16(c, aH, bh[2 * p], bh[2 * p + 1]);
                    mma_bf16(c, aH, bl[2 * p], bl[2 * p + 1]);
                    mma_bf16(c, aL, bh[2 * p], bh[2 * p + 1]);
                }
            }
        }
    }

    // epilogue: atomic-accumulate partial O (O pre-zeroed)
    const int g = lane >> 2, tq = lane & 3;
    const int ra = rowblk + wr + g;
#pragma unroll
    for (int j = 0; j < 8; j++) {
        atomicAdd(&O[(size_t)ra * D + 8 * j + 2 * tq],     acc[j][0]);
        atomicAdd(&O[(size_t)ra * D + 8 * j + 2 * tq + 1], acc[j][1]);
        atomicAdd(&O[(size_t)(ra + 8) * D + 8 * j + 2 * tq],     acc[j][2]);
        atomicAdd(&O[(size_t)(ra + 8) * D + 8 * j + 2 * tq + 1], acc[j][3]);
    }

    // last CTA resets PDL counters for the next graph replay
    if (tid == 0) {
        const int old = atomicAdd(&g_done, 1);
        if (old == NCH * NRB - 1) {
            g_prep[0] = 0; g_prep[1] = 0; g_prep[2] = 0; g_prep[3] = 0;
            __threadfence();
            atomicExch(&g_done, 0);
        }
    }
}

extern "C" void kernel_launch(void* const* d_in, const int* in_sizes, int n_in,
                              void* d_out, int out_size) {
    const float* q = (const float*)d_in[0];
    const float* k = (const float*)d_in[1];
    const float* v = (const float*)d_in[2];

    float* out   = (float*)d_out;          // [L, D]
    float* score = out + (size_t)L * D;    // [L, L]

    cudaFuncSetAttribute(pass1_kernel,
                         cudaFuncAttributeMaxDynamicSharedMemorySize, P1_SMEM);
    cudaFuncSetAttribute(pass2_kernel,
                         cudaFuncAttributeMaxDynamicSharedMemorySize, P2_SMEM);

    dim3 pgrid(PGX, 4);
    prep_kernel<<<pgrid, 256>>>(q, k, v, out);

    dim3 grid(NCH, L / BM);

    cudaLaunchAttribute attrs[1];
    attrs[0].id = cudaLaunchAttributeProgrammaticStreamSerialization;
    attrs[0].val.programmaticStreamSerializationAllowed = 1;

    // pass1 PDL-launched against prep (gated on g_prep flags)
    cudaLaunchConfig_t cfg1 = {};
    cfg1.gridDim  = grid;
    cfg1.blockDim = dim3(NT, 1, 1);
    cfg1.dynamicSmemBytes = P1_SMEM;
    cfg1.stream = 0;
    cfg1.attrs = attrs;
    cfg1.numAttrs = 1;
    if (cudaLaunchKernelEx(&cfg1, pass1_kernel, score) != cudaSuccess) {
        pass1_kernel<<<grid, NT, P1_SMEM>>>(score);        // serial fallback
    }

    // pass2 PDL-launched against pass1 (gated on g_cnt + V plane)
    cudaLaunchConfig_t cfg2 = {};
    cfg2.gridDim  = grid;
    cfg2.blockDim = dim3(NT, 1, 1);
    cfg2.dynamicSmemBytes = P2_SMEM;
    cfg2.stream = 0;
    cfg2.attrs = attrs;
    cfg2.numAttrs = 1;
    if (cudaLaunchKernelEx(&cfg2, pass2_kernel, score, out) != cudaSuccess) {
        pass2_kernel<<<grid, NT, P2_SMEM>>>(score, out);   // serial fallback
    }
}